// round 4
// baseline (speedup 1.0000x reference)
#include <cuda_runtime.h>
#include <cuda_bf16.h>

#define N_NODES 500000
#define N_ELEM  1000000
#define N_GROUP (N_ELEM / 4)          // 250000, exact

#define TPB     256
#define GRID_T  ((N_NODES + TPB - 1) / TPB)   // 1954 transpose blocks
#define GRID_E  1184                           // element kernel grid

// Scratch: packed, pre-scaled node displacements (u_phys), 16B/node.
__device__ float4 g_pred4[N_NODES];            // 8 MB
__device__ double g_partialsW[GRID_T];         // external work partials
__device__ double g_partialsU[GRID_E];         // strain energy partials
__device__ unsigned int g_count;               // zero-init; reset by last block

__device__ __forceinline__ double block_reduce_add(double v) {
    __shared__ double warp_sums[TPB / 32];
    int lane = threadIdx.x & 31;
    int wid  = threadIdx.x >> 5;

    #pragma unroll
    for (int off = 16; off > 0; off >>= 1)
        v += __shfl_down_sync(0xFFFFFFFFu, v, off);

    if (lane == 0) warp_sums[wid] = v;
    __syncthreads();

    v = (threadIdx.x < (TPB / 32)) ? warp_sums[threadIdx.x] : 0.0;
    if (wid == 0) {
        #pragma unroll
        for (int off = (TPB / 64); off > 0; off >>= 1)
            v += __shfl_down_sync(0xFFFFFFFFu, v, off);
    }
    __syncthreads();
    return v; // valid in thread 0
}

// Kernel 1: repack pred -> float4 (pre-scaled to u_phys) and compute
// -W_external = -sum(F_ext * u_phys) into per-block partials.
__global__ void __launch_bounds__(TPB)
pack_nodes_kernel(
    const float* __restrict__ pred,   // [N_NODES,3]
    const float* __restrict__ Fext,   // [N_NODES,3]
    const float* __restrict__ u_c_p,
    const float* __restrict__ th_c_p)
{
    const float u_c  = __ldg(u_c_p);
    const float th_c = __ldg(th_c_p);

    int n = blockIdx.x * TPB + threadIdx.x;
    double acc = 0.0;
    if (n < N_NODES) {
        long b = 3 * (long)n;
        float x  = pred[b + 0] * u_c;
        float y  = pred[b + 1] * u_c;
        float th = pred[b + 2] * th_c;
        g_pred4[n] = make_float4(x, y, th, 0.0f);

        float w = Fext[b + 0] * x + Fext[b + 1] * y + Fext[b + 2] * th;
        acc = -(double)w;
    }
    double bsum = block_reduce_add(acc);
    if (threadIdx.x == 0)
        g_partialsW[blockIdx.x] = bsum;
}

// Kernel 2: element strain energy with single-LDG.128 node gathers.
__global__ void __launch_bounds__(TPB)
elem_energy_kernel(
    const float* __restrict__ Lv,
    const float* __restrict__ Ev,
    const float* __restrict__ Av,
    const float* __restrict__ Iv,
    const float* __restrict__ dir,    // [N_ELEM,3] (c,0,s)
    const int*   __restrict__ conn,   // [N_ELEM,2]
    const float* __restrict__ F_c_p,
    const float* __restrict__ u_c_p,
    float*       __restrict__ out)
{
    const int tid     = blockIdx.x * TPB + threadIdx.x;
    const int nthread = GRID_E * TPB;

    double acc = 0.0;

    const int4*   c4 = (const int4*)conn;
    const float4* L4 = (const float4*)Lv;
    const float4* E4 = (const float4*)Ev;
    const float4* A4 = (const float4*)Av;
    const float4* I4 = (const float4*)Iv;
    const float4* d4 = (const float4*)dir;

    for (int g = tid; g < N_GROUP; g += nthread) {
        int4 cab0 = __ldg(&c4[2 * g + 0]);   // nA0,nB0,nA1,nB1
        int4 cab1 = __ldg(&c4[2 * g + 1]);   // nA2,nB2,nA3,nB3
        float4 Lq = __ldg(&L4[g]);
        float4 Eq = __ldg(&E4[g]);
        float4 Aq = __ldg(&A4[g]);
        float4 Iq = __ldg(&I4[g]);
        float4 D0 = __ldg(&d4[3 * g + 0]);   // c0,0,s0,c1
        float4 D1 = __ldg(&d4[3 * g + 1]);   // 0,s1,c2,0
        float4 D2 = __ldg(&d4[3 * g + 2]);   // s2,c3,0,s3

        // One 16B gather per node access (8 total), issued back-to-back.
        float4 PA0 = __ldg(&g_pred4[cab0.x]);
        float4 PB0 = __ldg(&g_pred4[cab0.y]);
        float4 PA1 = __ldg(&g_pred4[cab0.z]);
        float4 PB1 = __ldg(&g_pred4[cab0.w]);
        float4 PA2 = __ldg(&g_pred4[cab1.x]);
        float4 PB2 = __ldg(&g_pred4[cab1.y]);
        float4 PA3 = __ldg(&g_pred4[cab1.z]);
        float4 PB3 = __ldg(&g_pred4[cab1.w]);

        float4 PA[4] = { PA0, PA1, PA2, PA3 };
        float4 PB[4] = { PB0, PB1, PB2, PB3 };
        float  cc[4] = { D0.x, D0.w, D1.z, D2.y };
        float  ss[4] = { D0.z, D1.y, D2.x, D2.w };
        float  Ls[4] = { Lq.x, Lq.y, Lq.z, Lq.w };
        float  Es[4] = { Eq.x, Eq.y, Eq.z, Eq.w };
        float  As[4] = { Aq.x, Aq.y, Aq.z, Aq.w };
        float  Is[4] = { Iq.x, Iq.y, Iq.z, Iq.w };

        #pragma unroll
        for (int k = 0; k < 4; k++) {
            float c = cc[k], s = ss[k];
            float uA =  c * PA[k].x + s * PA[k].y;
            float wA = -s * PA[k].x + c * PA[k].y;
            float uB =  c * PB[k].x + s * PB[k].y;
            float wB = -s * PB[k].x + c * PB[k].y;
            float tA = PA[k].z, tB = PB[k].z;

            float E  = Es[k];
            float EA = E * As[k];
            float EI = E * Is[k];
            float invL  = 1.0f / Ls[k];
            float ea_L  = EA * invL;
            float ei_L  = EI * invL;
            float ei_L2 = ei_L * invL;
            float ei_L3 = ei_L2 * invL;

            float du = uA - uB;
            float dw = wA - wB;
            float ts = tA + tB;

            float q = ea_L * du * du
                    + 12.0f * ei_L3 * dw * dw
                    + 12.0f * ei_L2 * dw * ts
                    + 4.0f  * ei_L  * (tA * tA + tB * tB + tA * tB);
            acc += 0.5 * (double)q;
        }
    }

    double bsum = block_reduce_add(acc);

    __shared__ bool is_last;
    if (threadIdx.x == 0) {
        g_partialsU[blockIdx.x] = bsum;
        __threadfence();
        unsigned int done = atomicAdd(&g_count, 1u);
        is_last = (done == GRID_E - 1);
    }
    __syncthreads();

    if (is_last) {
        double v = 0.0;
        for (int b = threadIdx.x; b < GRID_E; b += TPB)
            v += g_partialsU[b];
        for (int b = threadIdx.x; b < GRID_T; b += TPB)
            v += g_partialsW[b];
        double total = block_reduce_add(v);
        if (threadIdx.x == 0) {
            double E_c = fmax((double)__ldg(F_c_p) * (double)__ldg(u_c_p), 1e-30);
            out[0] = (float)(total / E_c);
            __threadfence();
            g_count = 0;  // replay-safe reset
        }
    }
}

extern "C" void kernel_launch(void* const* d_in, const int* in_sizes, int n_in,
                              void* d_out, int out_size) {
    const float* pred  = (const float*)d_in[0];
    const float* Lv    = (const float*)d_in[1];
    const float* Ev    = (const float*)d_in[2];
    const float* Av    = (const float*)d_in[3];
    const float* Iv    = (const float*)d_in[4];
    const float* dir   = (const float*)d_in[5];
    const float* Fext  = (const float*)d_in[6];
    const float* u_c   = (const float*)d_in[7];
    const float* th_c  = (const float*)d_in[8];
    const float* F_c   = (const float*)d_in[9];
    const int*   conn  = (const int*)d_in[10];
    float* out = (float*)d_out;

    pack_nodes_kernel<<<GRID_T, TPB>>>(pred, Fext, u_c, th_c);
    elem_energy_kernel<<<GRID_E, TPB>>>(Lv, Ev, Av, Iv, dir, conn, F_c, u_c, out);
}

// round 5
// speedup vs baseline: 1.1697x; 1.1697x over previous
#include <cuda_runtime.h>
#include <cuda_bf16.h>

#define N_NODES 500000
#define N_ELEM  1000000
#define N_G2    (N_ELEM / 2)          // 500000 element-pairs

#define TPB     256
#define GRID_P  ((N_NODES / 4 + TPB - 1) / TPB)   // 489 pack blocks (4 nodes/thread)
#define GRID_E  ((N_G2 + TPB - 1) / TPB)          // 1954 element blocks

// Packed, pre-scaled node displacements (u_phys), 16B/node.
__device__ float4 g_pred4[N_NODES];               // 8 MB
__device__ double g_partialsW[GRID_P];
__device__ double g_partialsU[GRID_E];
__device__ unsigned int g_count;                  // zero-init; reset by last block

__device__ __forceinline__ double block_reduce_add(double v) {
    __shared__ double warp_sums[TPB / 32];
    int lane = threadIdx.x & 31;
    int wid  = threadIdx.x >> 5;

    #pragma unroll
    for (int off = 16; off > 0; off >>= 1)
        v += __shfl_down_sync(0xFFFFFFFFu, v, off);

    if (lane == 0) warp_sums[wid] = v;
    __syncthreads();

    v = (threadIdx.x < (TPB / 32)) ? warp_sums[threadIdx.x] : 0.0;
    if (wid == 0) {
        #pragma unroll
        for (int off = (TPB / 64); off > 0; off >>= 1)
            v += __shfl_down_sync(0xFFFFFFFFu, v, off);
    }
    __syncthreads();
    return v; // valid in thread 0
}

// Kernel 1: repack 4 nodes/thread: pred -> float4 u_phys; accumulate -W_ext.
__global__ void __launch_bounds__(TPB)
pack_nodes_kernel(
    const float* __restrict__ pred,   // [N_NODES,3]
    const float* __restrict__ Fext,   // [N_NODES,3]
    const float* __restrict__ u_c_p,
    const float* __restrict__ th_c_p)
{
    const float u_c  = __ldg(u_c_p);
    const float th_c = __ldg(th_c_p);

    const float4* p4 = (const float4*)pred;
    const float4* f4 = (const float4*)Fext;

    int t = blockIdx.x * TPB + threadIdx.x;   // group of 4 nodes
    double acc = 0.0;

    if (t < N_NODES / 4) {
        // 12 floats = 3 float4 per array (16B aligned: 4 nodes * 12B = 48B)
        float4 P0 = __ldg(&p4[3 * t + 0]);  // x0 y0 t0 x1
        float4 P1 = __ldg(&p4[3 * t + 1]);  // y1 t1 x2 y2
        float4 P2 = __ldg(&p4[3 * t + 2]);  // t2 x3 y3 t3
        float4 F0 = __ldg(&f4[3 * t + 0]);
        float4 F1 = __ldg(&f4[3 * t + 1]);
        float4 F2 = __ldg(&f4[3 * t + 2]);

        float4 n0 = make_float4(P0.x * u_c, P0.y * u_c, P0.z * th_c, 0.0f);
        float4 n1 = make_float4(P0.w * u_c, P1.x * u_c, P1.y * th_c, 0.0f);
        float4 n2 = make_float4(P1.z * u_c, P1.w * u_c, P2.x * th_c, 0.0f);
        float4 n3 = make_float4(P2.y * u_c, P2.z * u_c, P2.w * th_c, 0.0f);

        int n = 4 * t;
        g_pred4[n + 0] = n0;
        g_pred4[n + 1] = n1;
        g_pred4[n + 2] = n2;
        g_pred4[n + 3] = n3;

        float w = F0.x * n0.x + F0.y * n0.y + F0.z * n0.z
                + F0.w * n1.x + F1.x * n1.y + F1.y * n1.z
                + F1.z * n2.x + F1.w * n2.y + F2.x * n2.z
                + F2.y * n3.x + F2.z * n3.y + F2.w * n3.z;
        acc = -(double)w;
    }

    double bsum = block_reduce_add(acc);
    if (threadIdx.x == 0)
        g_partialsW[blockIdx.x] = bsum;
}

// Kernel 2: 2 elements/thread, single LDG.128 per node gather.
__global__ void __launch_bounds__(TPB, 6)
elem_energy_kernel(
    const float* __restrict__ Lv,
    const float* __restrict__ Ev,
    const float* __restrict__ Av,
    const float* __restrict__ Iv,
    const float* __restrict__ dir,    // [N_ELEM,3] (c,0,s)
    const int*   __restrict__ conn,   // [N_ELEM,2]
    const float* __restrict__ F_c_p,
    const float* __restrict__ u_c_p,
    float*       __restrict__ out)
{
    const int g = blockIdx.x * TPB + threadIdx.x;   // element pair index

    double acc = 0.0;

    if (g < N_G2) {
        const int4*   c4 = (const int4*)conn;
        const float2* L2p = (const float2*)Lv;
        const float2* E2p = (const float2*)Ev;
        const float2* A2p = (const float2*)Av;
        const float2* I2p = (const float2*)Iv;
        const float2* d2p = (const float2*)dir;

        int4   cab = __ldg(&c4[g]);        // nA0,nB0,nA1,nB1
        float2 Lq  = __ldg(&L2p[g]);
        float2 Eq  = __ldg(&E2p[g]);
        float2 Aq  = __ldg(&A2p[g]);
        float2 Iq  = __ldg(&I2p[g]);
        float2 D0  = __ldg(&d2p[3 * g + 0]);  // c0, 0
        float2 D1  = __ldg(&d2p[3 * g + 1]);  // s0, c1
        float2 D2  = __ldg(&d2p[3 * g + 2]);  // 0,  s1

        float4 PA0 = __ldg(&g_pred4[cab.x]);
        float4 PB0 = __ldg(&g_pred4[cab.y]);
        float4 PA1 = __ldg(&g_pred4[cab.z]);
        float4 PB1 = __ldg(&g_pred4[cab.w]);

        // element 0
        {
            float c = D0.x, s = D1.x;
            float uA =  c * PA0.x + s * PA0.y;
            float wA = -s * PA0.x + c * PA0.y;
            float uB =  c * PB0.x + s * PB0.y;
            float wB = -s * PB0.x + c * PB0.y;
            float tA = PA0.z, tB = PB0.z;

            float E  = Eq.x;
            float EA = E * Aq.x;
            float EI = E * Iq.x;
            float invL  = 1.0f / Lq.x;
            float ea_L  = EA * invL;
            float ei_L  = EI * invL;
            float ei_L2 = ei_L * invL;
            float ei_L3 = ei_L2 * invL;

            float du = uA - uB;
            float dw = wA - wB;
            float ts = tA + tB;

            float q = ea_L * du * du
                    + 12.0f * ei_L3 * dw * dw
                    + 12.0f * ei_L2 * dw * ts
                    + 4.0f  * ei_L  * (tA * tA + tB * tB + tA * tB);
            acc += 0.5 * (double)q;
        }
        // element 1
        {
            float c = D1.y, s = D2.y;
            float uA =  c * PA1.x + s * PA1.y;
            float wA = -s * PA1.x + c * PA1.y;
            float uB =  c * PB1.x + s * PB1.y;
            float wB = -s * PB1.x + c * PB1.y;
            float tA = PA1.z, tB = PB1.z;

            float E  = Eq.y;
            float EA = E * Aq.y;
            float EI = E * Iq.y;
            float invL  = 1.0f / Lq.y;
            float ea_L  = EA * invL;
            float ei_L  = EI * invL;
            float ei_L2 = ei_L * invL;
            float ei_L3 = ei_L2 * invL;

            float du = uA - uB;
            float dw = wA - wB;
            float ts = tA + tB;

            float q = ea_L * du * du
                    + 12.0f * ei_L3 * dw * dw
                    + 12.0f * ei_L2 * dw * ts
                    + 4.0f  * ei_L  * (tA * tA + tB * tB + tA * tB);
            acc += 0.5 * (double)q;
        }
    }

    double bsum = block_reduce_add(acc);

    __shared__ bool is_last;
    if (threadIdx.x == 0) {
        g_partialsU[blockIdx.x] = bsum;
        __threadfence();
        unsigned int done = atomicAdd(&g_count, 1u);
        is_last = (done == GRID_E - 1);
    }
    __syncthreads();

    if (is_last) {
        double v = 0.0;
        for (int b = threadIdx.x; b < GRID_E; b += TPB)
            v += g_partialsU[b];
        for (int b = threadIdx.x; b < GRID_P; b += TPB)
            v += g_partialsW[b];
        double total = block_reduce_add(v);
        if (threadIdx.x == 0) {
            double E_c = fmax((double)__ldg(F_c_p) * (double)__ldg(u_c_p), 1e-30);
            out[0] = (float)(total / E_c);
            __threadfence();
            g_count = 0;  // replay-safe reset
        }
    }
}

extern "C" void kernel_launch(void* const* d_in, const int* in_sizes, int n_in,
                              void* d_out, int out_size) {
    const float* pred  = (const float*)d_in[0];
    const float* Lv    = (const float*)d_in[1];
    const float* Ev    = (const float*)d_in[2];
    const float* Av    = (const float*)d_in[3];
    const float* Iv    = (const float*)d_in[4];
    const float* dir   = (const float*)d_in[5];
    const float* Fext  = (const float*)d_in[6];
    const float* u_c   = (const float*)d_in[7];
    const float* th_c  = (const float*)d_in[8];
    const float* F_c   = (const float*)d_in[9];
    const int*   conn  = (const int*)d_in[10];
    float* out = (float*)d_out;

    pack_nodes_kernel<<<GRID_P, TPB>>>(pred, Fext, u_c, th_c);
    elem_energy_kernel<<<GRID_E, TPB>>>(Lv, Ev, Av, Iv, dir, conn, F_c, u_c, out);
}

// round 6
// speedup vs baseline: 1.1787x; 1.0077x over previous
#include <cuda_runtime.h>
#include <cuda_bf16.h>

#define N_NODES 500000
#define N_ELEM  1000000
#define N_G2    (N_ELEM / 2)           // 500000 element pairs
#define NV4     ((N_NODES * 3) / 4)    // 375000 float4 node-work groups

#define TPB         128
#define GRID        (148 * 16)               // 2368 blocks
#define TOTAL_WARPS (GRID * (TPB / 32))      // 9472

__device__ double       g_acc;     // zero-init at load; reset by last warp
__device__ unsigned int g_count;   // zero-init at load; reset by last warp

__global__ void __launch_bounds__(TPB)
fused_energy_kernel(
    const float* __restrict__ pred,   // [N_NODES,3]
    const float* __restrict__ Lv,
    const float* __restrict__ Ev,
    const float* __restrict__ Av,
    const float* __restrict__ Iv,
    const float* __restrict__ dir,    // [N_ELEM,3] (c,0,s)
    const int*   __restrict__ conn,   // [N_ELEM,2]
    const float* __restrict__ Fext,   // [N_NODES,3]
    const float* __restrict__ u_c_p,
    const float* __restrict__ th_c_p,
    const float* __restrict__ F_c_p,
    float*       __restrict__ out)
{
    const float u_c  = __ldg(u_c_p);
    const float th_c = __ldg(th_c_p);

    const int tid = blockIdx.x * TPB + threadIdx.x;
    const int nth = GRID * TPB;

    double acc = 0.0;

    // ---- Element strain energy: 2 elements (one pair) per iteration ----
    const int4*   c4  = (const int4*)conn;
    const float2* L2p = (const float2*)Lv;
    const float2* E2p = (const float2*)Ev;
    const float2* A2p = (const float2*)Av;
    const float2* I2p = (const float2*)Iv;
    const float2* d2p = (const float2*)dir;

    for (int g = tid; g < N_G2; g += nth) {
        int4   cab = __ldg(&c4[g]);           // nA0,nB0,nA1,nB1
        float2 Lq  = __ldg(&L2p[g]);
        float2 Eq  = __ldg(&E2p[g]);
        float2 Aq  = __ldg(&A2p[g]);
        float2 Iq  = __ldg(&I2p[g]);
        float2 D0  = __ldg(&d2p[3 * g + 0]);  // c0, 0
        float2 D1  = __ldg(&d2p[3 * g + 1]);  // s0, c1
        float2 D2  = __ldg(&d2p[3 * g + 2]);  // 0,  s1

        const float* pA0 = pred + 3 * (long)cab.x;
        const float* pB0 = pred + 3 * (long)cab.y;
        const float* pA1 = pred + 3 * (long)cab.z;
        const float* pB1 = pred + 3 * (long)cab.w;

        float a0x = __ldg(&pA0[0]), a0y = __ldg(&pA0[1]), a0t = __ldg(&pA0[2]);
        float b0x = __ldg(&pB0[0]), b0y = __ldg(&pB0[1]), b0t = __ldg(&pB0[2]);
        float a1x = __ldg(&pA1[0]), a1y = __ldg(&pA1[1]), a1t = __ldg(&pA1[2]);
        float b1x = __ldg(&pB1[0]), b1y = __ldg(&pB1[1]), b1t = __ldg(&pB1[2]);

        float qsum;
        // element 0
        {
            float c = D0.x, s = D1.x;
            float x0 = a0x * u_c, y0 = a0y * u_c, tA = a0t * th_c;
            float x1 = b0x * u_c, y1 = b0y * u_c, tB = b0t * th_c;

            float uA =  c * x0 + s * y0;
            float wA = -s * x0 + c * y0;
            float uB =  c * x1 + s * y1;
            float wB = -s * x1 + c * y1;

            float E  = Eq.x;
            float EA = E * Aq.x;
            float EI = E * Iq.x;
            float invL  = 1.0f / Lq.x;
            float ea_L  = EA * invL;
            float ei_L  = EI * invL;
            float ei_L2 = ei_L * invL;
            float ei_L3 = ei_L2 * invL;

            float du = uA - uB;
            float dw = wA - wB;
            float ts = tA + tB;

            qsum = ea_L * du * du
                 + 12.0f * ei_L3 * dw * dw
                 + 12.0f * ei_L2 * dw * ts
                 + 4.0f  * ei_L  * (tA * tA + tB * tB + tA * tB);
        }
        // element 1
        {
            float c = D1.y, s = D2.y;
            float x0 = a1x * u_c, y0 = a1y * u_c, tA = a1t * th_c;
            float x1 = b1x * u_c, y1 = b1y * u_c, tB = b1t * th_c;

            float uA =  c * x0 + s * y0;
            float wA = -s * x0 + c * y0;
            float uB =  c * x1 + s * y1;
            float wB = -s * x1 + c * y1;

            float E  = Eq.y;
            float EA = E * Aq.y;
            float EI = E * Iq.y;
            float invL  = 1.0f / Lq.y;
            float ea_L  = EA * invL;
            float ei_L  = EI * invL;
            float ei_L2 = ei_L * invL;
            float ei_L3 = ei_L2 * invL;

            float du = uA - uB;
            float dw = wA - wB;
            float ts = tA + tB;

            qsum += ea_L * du * du
                  + 12.0f * ei_L3 * dw * dw
                  + 12.0f * ei_L2 * dw * ts
                  + 4.0f  * ei_L  * (tA * tA + tB * tB + tA * tB);
        }
        acc += 0.5 * (double)qsum;
    }

    // ---- External work: -sum(F_ext * u_phys), float4-vectorized ----
    {
        const float4* p4 = (const float4*)pred;
        const float4* f4 = (const float4*)Fext;
        for (int j = tid; j < NV4; j += nth) {
            float4 p = __ldg(&p4[j]);
            float4 f = __ldg(&f4[j]);
            int base = (4 * j) % 3;
            float s0 = (base == 2) ? th_c : u_c;
            float s1 = (base == 1) ? th_c : u_c;
            float s2 = (base == 0) ? th_c : u_c;
            float w = f.x * p.x * s0 + f.y * p.y * s1
                    + f.z * p.z * s2 + f.w * p.w * s0;
            acc -= (double)w;
        }
    }

    // ---- Warp-autonomous reduction: no barriers, no shared memory ----
    #pragma unroll
    for (int off = 16; off > 0; off >>= 1)
        acc += __shfl_down_sync(0xFFFFFFFFu, acc, off);

    if ((threadIdx.x & 31) == 0) {
        atomicAdd(&g_acc, acc);            // REDG-style accumulate
        __threadfence();
        unsigned int old = atomicAdd(&g_count, 1u);
        if (old == TOTAL_WARPS - 1) {
            // Last warp to finish: all other adds are globally visible.
            __threadfence();
            double total = atomicAdd(&g_acc, 0.0);   // atomic read
            double E_c = fmax((double)__ldg(F_c_p) * (double)u_c, 1e-30);
            out[0] = (float)(total / E_c);
            // Reset for next graph replay (kernel completes before next launch).
            g_acc   = 0.0;
            g_count = 0u;
            __threadfence();
        }
    }
}

extern "C" void kernel_launch(void* const* d_in, const int* in_sizes, int n_in,
                              void* d_out, int out_size) {
    const float* pred  = (const float*)d_in[0];
    const float* Lv    = (const float*)d_in[1];
    const float* Ev    = (const float*)d_in[2];
    const float* Av    = (const float*)d_in[3];
    const float* Iv    = (const float*)d_in[4];
    const float* dir   = (const float*)d_in[5];
    const float* Fext  = (const float*)d_in[6];
    const float* u_c   = (const float*)d_in[7];
    const float* th_c  = (const float*)d_in[8];
    const float* F_c   = (const float*)d_in[9];
    const int*   conn  = (const int*)d_in[10];
    float* out = (float*)d_out;

    fused_energy_kernel<<<GRID, TPB>>>(
        pred, Lv, Ev, Av, Iv, dir, conn, Fext, u_c, th_c, F_c, out);
}

// round 7
// speedup vs baseline: 1.2573x; 1.0667x over previous
#include <cuda_runtime.h>
#include <cuda_bf16.h>

#define N_NODES 500000
#define N_ELEM  1000000
#define N_G2    (N_ELEM / 2)                      // 500000 element pairs

#define TPB     256
#define GRID_P  ((N_NODES / 4 + TPB - 1) / TPB)  // 489 pack blocks
#define GRID_E  444                               // elem blocks (148*3)
#define NTH_E   (GRID_E * TPB)                    // 113664 threads
#define NITER   ((N_G2 + NTH_E - 1) / NTH_E)      // 5 (compile-time)

// Packed, pre-scaled node displacements (u_phys), 16B/node.
__device__ float4 g_pred4[N_NODES];               // 8 MB scratch
__device__ double g_partialsW[GRID_P];
__device__ double g_partialsU[GRID_E];
__device__ unsigned int g_count;                  // zero-init; reset by last block

__device__ __forceinline__ double block_reduce_add(double v) {
    __shared__ double warp_sums[TPB / 32];
    int lane = threadIdx.x & 31;
    int wid  = threadIdx.x >> 5;

    #pragma unroll
    for (int off = 16; off > 0; off >>= 1)
        v += __shfl_down_sync(0xFFFFFFFFu, v, off);

    if (lane == 0) warp_sums[wid] = v;
    __syncthreads();

    v = (threadIdx.x < (TPB / 32)) ? warp_sums[threadIdx.x] : 0.0;
    if (wid == 0) {
        #pragma unroll
        for (int off = (TPB / 64); off > 0; off >>= 1)
            v += __shfl_down_sync(0xFFFFFFFFu, v, off);
    }
    __syncthreads();
    return v; // valid in thread 0
}

// ---------------- Kernel 1: pack + external work ----------------
__global__ void __launch_bounds__(TPB)
pack_nodes_kernel(
    const float* __restrict__ pred,   // [N_NODES,3]
    const float* __restrict__ Fext,   // [N_NODES,3]
    const float* __restrict__ u_c_p,
    const float* __restrict__ th_c_p)
{
    const float u_c  = __ldg(u_c_p);
    const float th_c = __ldg(th_c_p);

    const float4* p4 = (const float4*)pred;
    const float4* f4 = (const float4*)Fext;

    int t = blockIdx.x * TPB + threadIdx.x;   // group of 4 nodes
    double acc = 0.0;

    if (t < N_NODES / 4) {
        float4 P0 = __ldg(&p4[3 * t + 0]);  // x0 y0 t0 x1
        float4 P1 = __ldg(&p4[3 * t + 1]);  // y1 t1 x2 y2
        float4 P2 = __ldg(&p4[3 * t + 2]);  // t2 x3 y3 t3
        float4 F0 = __ldg(&f4[3 * t + 0]);
        float4 F1 = __ldg(&f4[3 * t + 1]);
        float4 F2 = __ldg(&f4[3 * t + 2]);

        float4 n0 = make_float4(P0.x * u_c, P0.y * u_c, P0.z * th_c, 0.0f);
        float4 n1 = make_float4(P0.w * u_c, P1.x * u_c, P1.y * th_c, 0.0f);
        float4 n2 = make_float4(P1.z * u_c, P1.w * u_c, P2.x * th_c, 0.0f);
        float4 n3 = make_float4(P2.y * u_c, P2.z * u_c, P2.w * th_c, 0.0f);

        int n = 4 * t;
        g_pred4[n + 0] = n0;
        g_pred4[n + 1] = n1;
        g_pred4[n + 2] = n2;
        g_pred4[n + 3] = n3;

        float w = F0.x * n0.x + F0.y * n0.y + F0.z * n0.z
                + F0.w * n1.x + F1.x * n1.y + F1.y * n1.z
                + F1.z * n2.x + F1.w * n2.y + F2.x * n2.z
                + F2.y * n3.x + F2.z * n3.y + F2.w * n3.z;
        acc = -(double)w;
    }

    double bsum = block_reduce_add(acc);
    if (threadIdx.x == 0)
        g_partialsW[blockIdx.x] = bsum;
}

// ---------------- Kernel 2: pipelined element energy ----------------
struct Stream {
    int4   cab;          // nA0,nB0,nA1,nB1
    float2 L, E, A, I;
    float2 D0, D1, D2;   // (c0,0) (s0,c1) (0,s1)
    float  w;            // validity mask
};

struct Gath {
    float4 A0, B0, A1, B1;
};

__device__ __forceinline__ Stream load_stream(
    int g,
    const int4* __restrict__ c4,
    const float2* __restrict__ L2p, const float2* __restrict__ E2p,
    const float2* __restrict__ A2p, const float2* __restrict__ I2p,
    const float2* __restrict__ d2p)
{
    Stream S;
    bool v = (g < N_G2);
    int gg = v ? g : 0;
    S.cab = __ldg(&c4[gg]);
    S.L   = __ldg(&L2p[gg]);
    S.E   = __ldg(&E2p[gg]);
    S.A   = __ldg(&A2p[gg]);
    S.I   = __ldg(&I2p[gg]);
    S.D0  = __ldg(&d2p[3 * gg + 0]);
    S.D1  = __ldg(&d2p[3 * gg + 1]);
    S.D2  = __ldg(&d2p[3 * gg + 2]);
    S.w   = v ? 1.0f : 0.0f;
    return S;
}

__device__ __forceinline__ Gath load_gather(const int4 cab) {
    Gath G;
    G.A0 = __ldg(&g_pred4[cab.x]);
    G.B0 = __ldg(&g_pred4[cab.y]);
    G.A1 = __ldg(&g_pred4[cab.z]);
    G.B1 = __ldg(&g_pred4[cab.w]);
    return G;
}

__device__ __forceinline__ float one_elem(
    float c, float s, float4 PA, float4 PB,
    float L, float E, float A, float I)
{
    float uA =  c * PA.x + s * PA.y;
    float wA = -s * PA.x + c * PA.y;
    float uB =  c * PB.x + s * PB.y;
    float wB = -s * PB.x + c * PB.y;
    float tA = PA.z, tB = PB.z;

    float EA = E * A;
    float EI = E * I;
    float invL  = 1.0f / L;
    float ea_L  = EA * invL;
    float ei_L  = EI * invL;
    float ei_L2 = ei_L * invL;
    float ei_L3 = ei_L2 * invL;

    float du = uA - uB;
    float dw = wA - wB;
    float ts = tA + tB;

    return ea_L * du * du
         + 12.0f * ei_L3 * dw * dw
         + 12.0f * ei_L2 * dw * ts
         + 4.0f  * ei_L  * (tA * tA + tB * tB + tA * tB);
}

__device__ __forceinline__ float pair_energy(const Stream& S, const Gath& G) {
    float q = one_elem(S.D0.x, S.D1.x, G.A0, G.B0, S.L.x, S.E.x, S.A.x, S.I.x)
            + one_elem(S.D1.y, S.D2.y, G.A1, G.B1, S.L.y, S.E.y, S.A.y, S.I.y);
    return q * S.w;
}

__global__ void __launch_bounds__(TPB)
elem_energy_kernel(
    const float* __restrict__ Lv,
    const float* __restrict__ Ev,
    const float* __restrict__ Av,
    const float* __restrict__ Iv,
    const float* __restrict__ dir,
    const int*   __restrict__ conn,
    const float* __restrict__ F_c_p,
    const float* __restrict__ u_c_p,
    float*       __restrict__ out)
{
    const int tid = blockIdx.x * TPB + threadIdx.x;

    const int4*   c4  = (const int4*)conn;
    const float2* L2p = (const float2*)Lv;
    const float2* E2p = (const float2*)Ev;
    const float2* A2p = (const float2*)Av;
    const float2* I2p = (const float2*)Iv;
    const float2* d2p = (const float2*)dir;

    float acc = 0.0f;

    // Software pipeline: streams prefetched 2 iterations ahead,
    // gathers issued 1 iteration ahead of their use.
    Stream s_cur = load_stream(tid,          c4, L2p, E2p, A2p, I2p, d2p);
    Stream s_nxt = load_stream(tid + NTH_E,  c4, L2p, E2p, A2p, I2p, d2p);
    Gath   g_cur = load_gather(s_cur.cab);

    #pragma unroll
    for (int i = 0; i < NITER; i++) {
        Gath   g_nxt;
        Stream s_aft;
        if (i + 1 < NITER)
            g_nxt = load_gather(s_nxt.cab);          // cab arrived 1 iter ago
        if (i + 2 < NITER)
            s_aft = load_stream(tid + (i + 2) * NTH_E,
                                c4, L2p, E2p, A2p, I2p, d2p);

        acc += pair_energy(s_cur, g_cur);            // overlaps in-flight loads

        s_cur = s_nxt;
        if (i + 2 < NITER) s_nxt = s_aft;
        if (i + 1 < NITER) g_cur = g_nxt;
    }

    double bsum = block_reduce_add(0.5 * (double)acc);

    __shared__ bool is_last;
    if (threadIdx.x == 0) {
        g_partialsU[blockIdx.x] = bsum;
        __threadfence();
        unsigned int done = atomicAdd(&g_count, 1u);
        is_last = (done == GRID_E - 1);
    }
    __syncthreads();

    if (is_last) {
        double v = 0.0;
        for (int b = threadIdx.x; b < GRID_E; b += TPB)
            v += g_partialsU[b];
        for (int b = threadIdx.x; b < GRID_P; b += TPB)
            v += g_partialsW[b];
        double total = block_reduce_add(v);
        if (threadIdx.x == 0) {
            double E_c = fmax((double)__ldg(F_c_p) * (double)__ldg(u_c_p), 1e-30);
            out[0] = (float)(total / E_c);
            __threadfence();
            g_count = 0;  // replay-safe reset
        }
    }
}

extern "C" void kernel_launch(void* const* d_in, const int* in_sizes, int n_in,
                              void* d_out, int out_size) {
    const float* pred  = (const float*)d_in[0];
    const float* Lv    = (const float*)d_in[1];
    const float* Ev    = (const float*)d_in[2];
    const float* Av    = (const float*)d_in[3];
    const float* Iv    = (const float*)d_in[4];
    const float* dir   = (const float*)d_in[5];
    const float* Fext  = (const float*)d_in[6];
    const float* u_c   = (const float*)d_in[7];
    const float* th_c  = (const float*)d_in[8];
    const float* F_c   = (const float*)d_in[9];
    const int*   conn  = (const int*)d_in[10];
    float* out = (float*)d_out;

    pack_nodes_kernel<<<GRID_P, TPB>>>(pred, Fext, u_c, th_c);
    elem_energy_kernel<<<GRID_E, TPB>>>(Lv, Ev, Av, Iv, dir, conn, F_c, u_c, out);
}

// round 9
// speedup vs baseline: 1.4746x; 1.1728x over previous
#include <cuda_runtime.h>
#include <cuda_bf16.h>

#define N_NODES 500000
#define N_ELEM  1000000
#define N_G2    (N_ELEM / 2)          // 500000 element pairs
#define N_NG4   (N_NODES / 4)         // 125000 node groups of 4

#define TPB   256
#define GRID  296                     // 148 SMs * 2 blocks -> all co-resident
#define NTH   (GRID * TPB)            // 75776 threads
#define NITER ((N_G2 + NTH - 1) / NTH) // 7 (compile-time)

// Packed, pre-scaled node displacements (u_phys), 16B/node.
__device__ float4 g_pred4[N_NODES];               // 8 MB scratch
__device__ double g_partials[GRID];
__device__ unsigned int g_bar;    // barrier arrive counter (reset in-kernel)
__device__ unsigned int g_gen;    // barrier generation (monotonic across replays)
__device__ unsigned int g_count;  // finalize counter (reset in-kernel)

__device__ __forceinline__ double block_reduce_add(double v) {
    __shared__ double warp_sums[TPB / 32];
    int lane = threadIdx.x & 31;
    int wid  = threadIdx.x >> 5;

    #pragma unroll
    for (int off = 16; off > 0; off >>= 1)
        v += __shfl_down_sync(0xFFFFFFFFu, v, off);

    if (lane == 0) warp_sums[wid] = v;
    __syncthreads();

    v = (threadIdx.x < (TPB / 32)) ? warp_sums[threadIdx.x] : 0.0;
    if (wid == 0) {
        #pragma unroll
        for (int off = (TPB / 64); off > 0; off >>= 1)
            v += __shfl_down_sync(0xFFFFFFFFu, v, off);
    }
    __syncthreads();
    return v; // valid in thread 0
}

// ---- element-phase structs / helpers ----
struct Stream {
    int4   cab;          // nA0,nB0,nA1,nB1
    float2 L, E, A, I;
    float2 D0, D1, D2;   // (c0,0) (s0,c1) (0,s1)
    float  w;            // validity mask
};
struct Gath { float4 A0, B0, A1, B1; };

__device__ __forceinline__ Stream load_stream(
    int g,
    const int4* __restrict__ c4,
    const float2* __restrict__ L2p, const float2* __restrict__ E2p,
    const float2* __restrict__ A2p, const float2* __restrict__ I2p,
    const float2* __restrict__ d2p)
{
    Stream S;
    bool v = (g < N_G2);
    int gg = v ? g : 0;
    S.cab = __ldg(&c4[gg]);
    S.L   = __ldg(&L2p[gg]);
    S.E   = __ldg(&E2p[gg]);
    S.A   = __ldg(&A2p[gg]);
    S.I   = __ldg(&I2p[gg]);
    S.D0  = __ldg(&d2p[3 * gg + 0]);
    S.D1  = __ldg(&d2p[3 * gg + 1]);
    S.D2  = __ldg(&d2p[3 * gg + 2]);
    S.w   = v ? 1.0f : 0.0f;
    return S;
}

// COHERENT gather: g_pred4 is written by this kernel (phase 1), so it must
// NOT be read through the non-coherent __ldg path. Plain loads are L2-coherent
// and local L1 can only hold lines this SM itself wrote (which are correct).
__device__ __forceinline__ Gath load_gather(const int4 cab) {
    Gath G;
    G.A0 = g_pred4[cab.x];
    G.B0 = g_pred4[cab.y];
    G.A1 = g_pred4[cab.z];
    G.B1 = g_pred4[cab.w];
    return G;
}

__device__ __forceinline__ float one_elem(
    float c, float s, float4 PA, float4 PB,
    float L, float E, float A, float I)
{
    float uA =  c * PA.x + s * PA.y;
    float wA = -s * PA.x + c * PA.y;
    float uB =  c * PB.x + s * PB.y;
    float wB = -s * PB.x + c * PB.y;
    float tA = PA.z, tB = PB.z;

    float EA = E * A;
    float EI = E * I;
    float invL  = 1.0f / L;
    float ea_L  = EA * invL;
    float ei_L  = EI * invL;
    float ei_L2 = ei_L * invL;
    float ei_L3 = ei_L2 * invL;

    float du = uA - uB;
    float dw = wA - wB;
    float ts = tA + tB;

    return ea_L * du * du
         + 12.0f * ei_L3 * dw * dw
         + 12.0f * ei_L2 * dw * ts
         + 4.0f  * ei_L  * (tA * tA + tB * tB + tA * tB);
}

__device__ __forceinline__ float pair_energy(const Stream& S, const Gath& G) {
    float q = one_elem(S.D0.x, S.D1.x, G.A0, G.B0, S.L.x, S.E.x, S.A.x, S.I.x)
            + one_elem(S.D1.y, S.D2.y, G.A1, G.B1, S.L.y, S.E.y, S.A.y, S.I.y);
    return q * S.w;
}

__global__ void __launch_bounds__(TPB, 2)
fused_energy_kernel(
    const float* __restrict__ pred,   // [N_NODES,3]
    const float* __restrict__ Lv,
    const float* __restrict__ Ev,
    const float* __restrict__ Av,
    const float* __restrict__ Iv,
    const float* __restrict__ dir,    // [N_ELEM,3]
    const int*   __restrict__ conn,   // [N_ELEM,2]
    const float* __restrict__ Fext,   // [N_NODES,3]
    const float* __restrict__ u_c_p,
    const float* __restrict__ th_c_p,
    const float* __restrict__ F_c_p,
    float*       __restrict__ out)
{
    const float u_c  = __ldg(u_c_p);
    const float th_c = __ldg(th_c_p);

    const int tid = blockIdx.x * TPB + threadIdx.x;

    double acc = 0.0;   // -W_ext contribution; energy added at end

    // ---------------- Phase 1: pack nodes + external work ----------------
    {
        const float4* p4 = (const float4*)pred;
        const float4* f4 = (const float4*)Fext;

        for (int t = tid; t < N_NG4; t += NTH) {
            float4 P0 = __ldg(&p4[3 * t + 0]);  // x0 y0 t0 x1
            float4 P1 = __ldg(&p4[3 * t + 1]);  // y1 t1 x2 y2
            float4 P2 = __ldg(&p4[3 * t + 2]);  // t2 x3 y3 t3
            float4 F0 = __ldg(&f4[3 * t + 0]);
            float4 F1 = __ldg(&f4[3 * t + 1]);
            float4 F2 = __ldg(&f4[3 * t + 2]);

            float4 n0 = make_float4(P0.x * u_c, P0.y * u_c, P0.z * th_c, 0.0f);
            float4 n1 = make_float4(P0.w * u_c, P1.x * u_c, P1.y * th_c, 0.0f);
            float4 n2 = make_float4(P1.z * u_c, P1.w * u_c, P2.x * th_c, 0.0f);
            float4 n3 = make_float4(P2.y * u_c, P2.z * u_c, P2.w * th_c, 0.0f);

            int n = 4 * t;
            g_pred4[n + 0] = n0;
            g_pred4[n + 1] = n1;
            g_pred4[n + 2] = n2;
            g_pred4[n + 3] = n3;

            float w = F0.x * n0.x + F0.y * n0.y + F0.z * n0.z
                    + F0.w * n1.x + F1.x * n1.y + F1.y * n1.z
                    + F1.z * n2.x + F1.w * n2.y + F2.x * n2.z
                    + F2.y * n3.x + F2.z * n3.y + F2.w * n3.z;
            acc -= (double)w;
        }
    }

    // ---------------- Prefetch phase-2 streams (pack-independent) --------
    const int4*   c4  = (const int4*)conn;
    const float2* L2p = (const float2*)Lv;
    const float2* E2p = (const float2*)Ev;
    const float2* A2p = (const float2*)Av;
    const float2* I2p = (const float2*)Iv;
    const float2* d2p = (const float2*)dir;

    Stream s_cur = load_stream(tid,       c4, L2p, E2p, A2p, I2p, d2p);
    Stream s_nxt = load_stream(tid + NTH, c4, L2p, E2p, A2p, I2p, d2p);

    // ---------------- Grid-wide barrier (all 296 blocks co-resident) -----
    __syncthreads();                 // whole block done with phase-1 stores
    __shared__ unsigned int bar_gen;
    if (threadIdx.x == 0) {
        __threadfence();             // publish g_pred4 stores to L2
        unsigned int start = *(volatile unsigned int*)&g_gen;
        unsigned int old = atomicAdd(&g_bar, 1u);
        if (old == GRID - 1) {
            g_bar = 0;               // reset for next replay
            __threadfence();
            atomicAdd(&g_gen, 1u);   // release everyone
        } else {
            while (*(volatile unsigned int*)&g_gen == start) { }
        }
        bar_gen = 1;
    }
    __syncthreads();
    __threadfence();                 // acquire: order later reads after release
    (void)bar_gen;

    // ---------------- Phase 2: pipelined element energy ------------------
    float facc = 0.0f;
    Gath g_cur = load_gather(s_cur.cab);

    #pragma unroll
    for (int i = 0; i < NITER; i++) {
        Gath   g_nxt;
        Stream s_aft;
        if (i + 1 < NITER)
            g_nxt = load_gather(s_nxt.cab);            // cab arrived 1 iter ago
        if (i + 2 < NITER)
            s_aft = load_stream(tid + (i + 2) * NTH,
                                c4, L2p, E2p, A2p, I2p, d2p);

        facc += pair_energy(s_cur, g_cur);             // overlaps in-flight loads

        s_cur = s_nxt;
        if (i + 2 < NITER) s_nxt = s_aft;
        if (i + 1 < NITER) g_cur = g_nxt;
    }

    acc += 0.5 * (double)facc;

    // ---------------- Final reduction ------------------------------------
    double bsum = block_reduce_add(acc);

    __shared__ bool is_last;
    if (threadIdx.x == 0) {
        g_partials[blockIdx.x] = bsum;
        __threadfence();
        unsigned int done = atomicAdd(&g_count, 1u);
        is_last = (done == GRID - 1);
    }
    __syncthreads();

    if (is_last) {
        double v = 0.0;
        for (int b = threadIdx.x; b < GRID; b += TPB)
            v += g_partials[b];
        double total = block_reduce_add(v);
        if (threadIdx.x == 0) {
            double E_c = fmax((double)__ldg(F_c_p) * (double)u_c, 1e-30);
            out[0] = (float)(total / E_c);
            __threadfence();
            g_count = 0;  // replay-safe reset
        }
    }
}

extern "C" void kernel_launch(void* const* d_in, const int* in_sizes, int n_in,
                              void* d_out, int out_size) {
    const float* pred  = (const float*)d_in[0];
    const float* Lv    = (const float*)d_in[1];
    const float* Ev    = (const float*)d_in[2];
    const float* Av    = (const float*)d_in[3];
    const float* Iv    = (const float*)d_in[4];
    const float* dir   = (const float*)d_in[5];
    const float* Fext  = (const float*)d_in[6];
    const float* u_c   = (const float*)d_in[7];
    const float* th_c  = (const float*)d_in[8];
    const float* F_c   = (const float*)d_in[9];
    const int*   conn  = (const int*)d_in[10];
    float* out = (float*)d_out;

    fused_energy_kernel<<<GRID, TPB>>>(
        pred, Lv, Ev, Av, Iv, dir, conn, Fext, u_c, th_c, F_c, out);
}

// round 10
// speedup vs baseline: 1.4766x; 1.0014x over previous
#include <cuda_runtime.h>
#include <cuda_bf16.h>

#define N_NODES 500000
#define N_ELEM  1000000
#define N_G2    (N_ELEM / 2)          // 500000 element pairs
#define N_NG4   (N_NODES / 4)         // 125000 node groups of 4

#define TPB   256
#define GRID  296                     // 148 SMs * 2 blocks -> all co-resident
#define NTH   (GRID * TPB)            // 75776 threads
#define NITER ((N_G2 + NTH - 1) / NTH) // 7 (compile-time)

// Packed, pre-scaled node displacements (u_phys), 16B/node.
__device__ float4 g_pred4[N_NODES];               // 8 MB scratch
__device__ double g_partials[GRID];
__device__ unsigned int g_bar;    // barrier arrive counter (reset in-kernel)
__device__ unsigned int g_gen;    // barrier generation (monotonic across replays)
__device__ unsigned int g_count;  // finalize counter (reset in-kernel)

__device__ __forceinline__ double block_reduce_add(double v) {
    __shared__ double warp_sums[TPB / 32];
    int lane = threadIdx.x & 31;
    int wid  = threadIdx.x >> 5;

    #pragma unroll
    for (int off = 16; off > 0; off >>= 1)
        v += __shfl_down_sync(0xFFFFFFFFu, v, off);

    if (lane == 0) warp_sums[wid] = v;
    __syncthreads();

    v = (threadIdx.x < (TPB / 32)) ? warp_sums[threadIdx.x] : 0.0;
    if (wid == 0) {
        #pragma unroll
        for (int off = (TPB / 64); off > 0; off >>= 1)
            v += __shfl_down_sync(0xFFFFFFFFu, v, off);
    }
    __syncthreads();
    return v; // valid in thread 0
}

// ---- element-phase structs / helpers ----
struct Stream {
    int4   cab;          // nA0,nB0,nA1,nB1
    float2 L, E, A, I;
    float2 D0, D1, D2;   // (c0,0) (s0,c1) (0,s1)
    float  w;            // validity mask
};
struct Gath { float4 A0, B0, A1, B1; };

__device__ __forceinline__ Stream load_stream(
    int g,
    const int4* __restrict__ c4,
    const float2* __restrict__ L2p, const float2* __restrict__ E2p,
    const float2* __restrict__ A2p, const float2* __restrict__ I2p,
    const float2* __restrict__ d2p)
{
    Stream S;
    bool v = (g < N_G2);
    int gg = v ? g : 0;
    S.cab = __ldg(&c4[gg]);
    S.L   = __ldg(&L2p[gg]);
    S.E   = __ldg(&E2p[gg]);
    S.A   = __ldg(&A2p[gg]);
    S.I   = __ldg(&I2p[gg]);
    S.D0  = __ldg(&d2p[3 * gg + 0]);
    S.D1  = __ldg(&d2p[3 * gg + 1]);
    S.D2  = __ldg(&d2p[3 * gg + 2]);
    S.w   = v ? 1.0f : 0.0f;
    return S;
}

// COHERENT gather (plain LDG): g_pred4 is written by this kernel in phase 1,
// so it must not go through the non-coherent __ldg path.
__device__ __forceinline__ Gath load_gather(const int4 cab) {
    Gath G;
    G.A0 = g_pred4[cab.x];
    G.B0 = g_pred4[cab.y];
    G.A1 = g_pred4[cab.z];
    G.B1 = g_pred4[cab.w];
    return G;
}

__device__ __forceinline__ float one_elem(
    float c, float s, float4 PA, float4 PB,
    float L, float E, float A, float I)
{
    float uA =  c * PA.x + s * PA.y;
    float wA = -s * PA.x + c * PA.y;
    float uB =  c * PB.x + s * PB.y;
    float wB = -s * PB.x + c * PB.y;
    float tA = PA.z, tB = PB.z;

    float EA = E * A;
    float EI = E * I;
    float invL  = 1.0f / L;
    float ea_L  = EA * invL;
    float ei_L  = EI * invL;
    float ei_L2 = ei_L * invL;
    float ei_L3 = ei_L2 * invL;

    float du = uA - uB;
    float dw = wA - wB;
    float ts = tA + tB;

    return ea_L * du * du
         + 12.0f * ei_L3 * dw * dw
         + 12.0f * ei_L2 * dw * ts
         + 4.0f  * ei_L  * (tA * tA + tB * tB + tA * tB);
}

__device__ __forceinline__ float pair_energy(const Stream& S, const Gath& G) {
    float q = one_elem(S.D0.x, S.D1.x, G.A0, G.B0, S.L.x, S.E.x, S.A.x, S.I.x)
            + one_elem(S.D1.y, S.D2.y, G.A1, G.B1, S.L.y, S.E.y, S.A.y, S.I.y);
    return q * S.w;
}

__global__ void __launch_bounds__(TPB, 2)
fused_energy_kernel(
    const float* __restrict__ pred,   // [N_NODES,3]
    const float* __restrict__ Lv,
    const float* __restrict__ Ev,
    const float* __restrict__ Av,
    const float* __restrict__ Iv,
    const float* __restrict__ dir,    // [N_ELEM,3]
    const int*   __restrict__ conn,   // [N_ELEM,2]
    const float* __restrict__ Fext,   // [N_NODES,3]
    const float* __restrict__ u_c_p,
    const float* __restrict__ th_c_p,
    const float* __restrict__ F_c_p,
    float*       __restrict__ out)
{
    const float u_c  = __ldg(u_c_p);
    const float th_c = __ldg(th_c_p);

    const int tid = blockIdx.x * TPB + threadIdx.x;

    double acc = 0.0;   // -W_ext contribution; energy added at end

    // ---------------- Phase 1: pack nodes + external work ----------------
    {
        const float4* p4 = (const float4*)pred;
        const float4* f4 = (const float4*)Fext;

        for (int t = tid; t < N_NG4; t += NTH) {
            float4 P0 = __ldg(&p4[3 * t + 0]);  // x0 y0 t0 x1
            float4 P1 = __ldg(&p4[3 * t + 1]);  // y1 t1 x2 y2
            float4 P2 = __ldg(&p4[3 * t + 2]);  // t2 x3 y3 t3
            float4 F0 = __ldg(&f4[3 * t + 0]);
            float4 F1 = __ldg(&f4[3 * t + 1]);
            float4 F2 = __ldg(&f4[3 * t + 2]);

            float4 n0 = make_float4(P0.x * u_c, P0.y * u_c, P0.z * th_c, 0.0f);
            float4 n1 = make_float4(P0.w * u_c, P1.x * u_c, P1.y * th_c, 0.0f);
            float4 n2 = make_float4(P1.z * u_c, P1.w * u_c, P2.x * th_c, 0.0f);
            float4 n3 = make_float4(P2.y * u_c, P2.z * u_c, P2.w * th_c, 0.0f);

            int n = 4 * t;
            g_pred4[n + 0] = n0;
            g_pred4[n + 1] = n1;
            g_pred4[n + 2] = n2;
            g_pred4[n + 3] = n3;

            float w = F0.x * n0.x + F0.y * n0.y + F0.z * n0.z
                    + F0.w * n1.x + F1.x * n1.y + F1.y * n1.z
                    + F1.z * n2.x + F1.w * n2.y + F2.x * n2.z
                    + F2.y * n3.x + F2.z * n3.y + F2.w * n3.z;
            acc -= (double)w;
        }
    }

    // ---------------- Prefetch 3 iterations of streams (pack-independent)
    const int4*   c4  = (const int4*)conn;
    const float2* L2p = (const float2*)Lv;
    const float2* E2p = (const float2*)Ev;
    const float2* A2p = (const float2*)Av;
    const float2* I2p = (const float2*)Iv;
    const float2* d2p = (const float2*)dir;

    Stream sA = load_stream(tid,           c4, L2p, E2p, A2p, I2p, d2p);
    Stream sB = load_stream(tid + NTH,     c4, L2p, E2p, A2p, I2p, d2p);
    Stream sC = load_stream(tid + 2 * NTH, c4, L2p, E2p, A2p, I2p, d2p);

    // ---------------- Grid-wide barrier (all 296 blocks co-resident) -----
    __syncthreads();                 // whole block done with phase-1 stores
    __shared__ unsigned int bar_gen;
    if (threadIdx.x == 0) {
        __threadfence();             // publish g_pred4 stores to L2
        unsigned int start = *(volatile unsigned int*)&g_gen;
        unsigned int old = atomicAdd(&g_bar, 1u);
        if (old == GRID - 1) {
            g_bar = 0;               // reset for next replay
            __threadfence();
            atomicAdd(&g_gen, 1u);   // release everyone
        } else {
            while (*(volatile unsigned int*)&g_gen == start) { }
        }
        bar_gen = 1;
    }
    __syncthreads();
    __threadfence();                 // acquire side
    (void)bar_gen;

    // ---------------- Phase 2: depth-2 pipelined element energy ----------
    // Steady state at iter i: streams i,i+1,i+2 resident; gathers i,i+1 in
    // flight/resident; issue gather(i+2) and stream(i+3) before compute(i).
    float facc = 0.0f;
    Gath gA = load_gather(sA.cab);   // for iter 0
    Gath gB = load_gather(sB.cab);   // for iter 1

    #pragma unroll
    for (int i = 0; i < NITER; i++) {
        Stream sD;
        Gath   gC;
        if (i + 3 < NITER)
            sD = load_stream(tid + (i + 3) * NTH,
                             c4, L2p, E2p, A2p, I2p, d2p);
        if (i + 2 < NITER)
            gC = load_gather(sC.cab);          // cab arrived 2+ iters ago

        facc += pair_energy(sA, gA);           // overlaps in-flight loads

        sA = sB; sB = sC;
        if (i + 3 < NITER) sC = sD;
        gA = gB;
        if (i + 2 < NITER) gB = gC;
    }

    acc += 0.5 * (double)facc;

    // ---------------- Final reduction ------------------------------------
    double bsum = block_reduce_add(acc);

    __shared__ bool is_last;
    if (threadIdx.x == 0) {
        g_partials[blockIdx.x] = bsum;
        __threadfence();
        unsigned int done = atomicAdd(&g_count, 1u);
        is_last = (done == GRID - 1);
    }
    __syncthreads();

    if (is_last) {
        double v = 0.0;
        for (int b = threadIdx.x; b < GRID; b += TPB)
            v += g_partials[b];
        double total = block_reduce_add(v);
        if (threadIdx.x == 0) {
            double E_c = fmax((double)__ldg(F_c_p) * (double)u_c, 1e-30);
            out[0] = (float)(total / E_c);
            __threadfence();
            g_count = 0;  // replay-safe reset
        }
    }
}

extern "C" void kernel_launch(void* const* d_in, const int* in_sizes, int n_in,
                              void* d_out, int out_size) {
    const float* pred  = (const float*)d_in[0];
    const float* Lv    = (const float*)d_in[1];
    const float* Ev    = (const float*)d_in[2];
    const float* Av    = (const float*)d_in[3];
    const float* Iv    = (const float*)d_in[4];
    const float* dir   = (const float*)d_in[5];
    const float* Fext  = (const float*)d_in[6];
    const float* u_c   = (const float*)d_in[7];
    const float* th_c  = (const float*)d_in[8];
    const float* F_c   = (const float*)d_in[9];
    const int*   conn  = (const int*)d_in[10];
    float* out = (float*)d_out;

    fused_energy_kernel<<<GRID, TPB>>>(
        pred, Lv, Ev, Av, Iv, dir, conn, Fext, u_c, th_c, F_c, out);
}

// round 11
// speedup vs baseline: 1.4787x; 1.0014x over previous
#include <cuda_runtime.h>
#include <cuda_bf16.h>

#define N_NODES 500000
#define N_ELEM  1000000
#define N_G2    (N_ELEM / 2)          // 500000 element pairs
#define N_NG4   (N_NODES / 4)         // 125000 node groups of 4

#define TPB   256
#define GRID  296                     // 148 SMs * 2 blocks -> all co-resident
#define NTH   (GRID * TPB)            // 75776 threads
#define NITER ((N_G2 + NTH - 1) / NTH) // 7 (compile-time)

// Packed, pre-scaled node displacements (u_phys), 16B/node.
__device__ float4 g_pred4[N_NODES];               // 8 MB scratch
__device__ double g_partials[GRID];
__device__ unsigned int g_bar;    // barrier arrive counter (reset in-kernel)
__device__ unsigned int g_gen;    // barrier generation (monotonic across replays)
__device__ unsigned int g_count;  // finalize counter (reset in-kernel)

__device__ __forceinline__ double block_reduce_add(double v) {
    __shared__ double warp_sums[TPB / 32];
    int lane = threadIdx.x & 31;
    int wid  = threadIdx.x >> 5;

    #pragma unroll
    for (int off = 16; off > 0; off >>= 1)
        v += __shfl_down_sync(0xFFFFFFFFu, v, off);

    if (lane == 0) warp_sums[wid] = v;
    __syncthreads();

    v = (threadIdx.x < (TPB / 32)) ? warp_sums[threadIdx.x] : 0.0;
    if (wid == 0) {
        #pragma unroll
        for (int off = (TPB / 64); off > 0; off >>= 1)
            v += __shfl_down_sync(0xFFFFFFFFu, v, off);
    }
    __syncthreads();
    return v; // valid in thread 0
}

// ---- element-phase structs / helpers ----
struct Stream {
    int4   cab;          // nA0,nB0,nA1,nB1
    float2 L, E, A, I;
    float2 D0, D1, D2;   // (c0,0) (s0,c1) (0,s1)
    float  w;            // validity mask
};
struct Gath { float4 A0, B0, A1, B1; };

__device__ __forceinline__ Stream load_stream(
    int g,
    const int4* __restrict__ c4,
    const float2* __restrict__ L2p, const float2* __restrict__ E2p,
    const float2* __restrict__ A2p, const float2* __restrict__ I2p,
    const float2* __restrict__ d2p)
{
    Stream S;
    bool v = (g < N_G2);
    int gg = v ? g : 0;
    S.cab = __ldg(&c4[gg]);
    S.L   = __ldg(&L2p[gg]);
    S.E   = __ldg(&E2p[gg]);
    S.A   = __ldg(&A2p[gg]);
    S.I   = __ldg(&I2p[gg]);
    S.D0  = __ldg(&d2p[3 * gg + 0]);
    S.D1  = __ldg(&d2p[3 * gg + 1]);
    S.D2  = __ldg(&d2p[3 * gg + 2]);
    S.w   = v ? 1.0f : 0.0f;
    return S;
}

// Gather with ld.global.cg: L2-coherent (g_pred4 was written this launch)
// and bypasses L1 entirely -> no L1 line allocation / replay cost.
__device__ __forceinline__ float4 ldcg_f4(const float4* p) {
    float4 r;
    asm volatile("ld.global.cg.v4.f32 {%0,%1,%2,%3}, [%4];"
                 : "=f"(r.x), "=f"(r.y), "=f"(r.z), "=f"(r.w)
                 : "l"(p));
    return r;
}

__device__ __forceinline__ Gath load_gather(const int4 cab) {
    Gath G;
    G.A0 = ldcg_f4(&g_pred4[cab.x]);
    G.B0 = ldcg_f4(&g_pred4[cab.y]);
    G.A1 = ldcg_f4(&g_pred4[cab.z]);
    G.B1 = ldcg_f4(&g_pred4[cab.w]);
    return G;
}

__device__ __forceinline__ float one_elem(
    float c, float s, float4 PA, float4 PB,
    float L, float E, float A, float I)
{
    float uA =  c * PA.x + s * PA.y;
    float wA = -s * PA.x + c * PA.y;
    float uB =  c * PB.x + s * PB.y;
    float wB = -s * PB.x + c * PB.y;
    float tA = PA.z, tB = PB.z;

    float EA = E * A;
    float EI = E * I;
    float invL  = 1.0f / L;
    float ea_L  = EA * invL;
    float ei_L  = EI * invL;
    float ei_L2 = ei_L * invL;
    float ei_L3 = ei_L2 * invL;

    float du = uA - uB;
    float dw = wA - wB;
    float ts = tA + tB;

    return ea_L * du * du
         + 12.0f * ei_L3 * dw * dw
         + 12.0f * ei_L2 * dw * ts
         + 4.0f  * ei_L  * (tA * tA + tB * tB + tA * tB);
}

__device__ __forceinline__ float pair_energy(const Stream& S, const Gath& G) {
    float q = one_elem(S.D0.x, S.D1.x, G.A0, G.B0, S.L.x, S.E.x, S.A.x, S.I.x)
            + one_elem(S.D1.y, S.D2.y, G.A1, G.B1, S.L.y, S.E.y, S.A.y, S.I.y);
    return q * S.w;
}

__global__ void __launch_bounds__(TPB, 2)
fused_energy_kernel(
    const float* __restrict__ pred,   // [N_NODES,3]
    const float* __restrict__ Lv,
    const float* __restrict__ Ev,
    const float* __restrict__ Av,
    const float* __restrict__ Iv,
    const float* __restrict__ dir,    // [N_ELEM,3]
    const int*   __restrict__ conn,   // [N_ELEM,2]
    const float* __restrict__ Fext,   // [N_NODES,3]
    const float* __restrict__ u_c_p,
    const float* __restrict__ th_c_p,
    const float* __restrict__ F_c_p,
    float*       __restrict__ out)
{
    const float u_c  = __ldg(u_c_p);
    const float th_c = __ldg(th_c_p);

    const int tid = blockIdx.x * TPB + threadIdx.x;

    double acc = 0.0;   // -W_ext contribution; energy added at end

    // ---------------- Phase 1: pack nodes + external work ----------------
    {
        const float4* p4 = (const float4*)pred;
        const float4* f4 = (const float4*)Fext;

        for (int t = tid; t < N_NG4; t += NTH) {
            float4 P0 = __ldg(&p4[3 * t + 0]);  // x0 y0 t0 x1
            float4 P1 = __ldg(&p4[3 * t + 1]);  // y1 t1 x2 y2
            float4 P2 = __ldg(&p4[3 * t + 2]);  // t2 x3 y3 t3
            float4 F0 = __ldg(&f4[3 * t + 0]);
            float4 F1 = __ldg(&f4[3 * t + 1]);
            float4 F2 = __ldg(&f4[3 * t + 2]);

            float4 n0 = make_float4(P0.x * u_c, P0.y * u_c, P0.z * th_c, 0.0f);
            float4 n1 = make_float4(P0.w * u_c, P1.x * u_c, P1.y * th_c, 0.0f);
            float4 n2 = make_float4(P1.z * u_c, P1.w * u_c, P2.x * th_c, 0.0f);
            float4 n3 = make_float4(P2.y * u_c, P2.z * u_c, P2.w * th_c, 0.0f);

            int n = 4 * t;
            g_pred4[n + 0] = n0;
            g_pred4[n + 1] = n1;
            g_pred4[n + 2] = n2;
            g_pred4[n + 3] = n3;

            float w = F0.x * n0.x + F0.y * n0.y + F0.z * n0.z
                    + F0.w * n1.x + F1.x * n1.y + F1.y * n1.z
                    + F1.z * n2.x + F1.w * n2.y + F2.x * n2.z
                    + F2.y * n3.x + F2.z * n3.y + F2.w * n3.z;
            acc -= (double)w;
        }
    }

    // ---------------- Prefetch phase-2 streams (pack-independent) --------
    const int4*   c4  = (const int4*)conn;
    const float2* L2p = (const float2*)Lv;
    const float2* E2p = (const float2*)Ev;
    const float2* A2p = (const float2*)Av;
    const float2* I2p = (const float2*)Iv;
    const float2* d2p = (const float2*)dir;

    Stream s_cur = load_stream(tid,       c4, L2p, E2p, A2p, I2p, d2p);
    Stream s_nxt = load_stream(tid + NTH, c4, L2p, E2p, A2p, I2p, d2p);

    // ---------------- Grid-wide barrier (all 296 blocks co-resident) -----
    __syncthreads();                 // whole block done with phase-1 stores
    __shared__ unsigned int bar_gen;
    if (threadIdx.x == 0) {
        __threadfence();             // publish g_pred4 stores to L2
        unsigned int start = *(volatile unsigned int*)&g_gen;
        unsigned int old = atomicAdd(&g_bar, 1u);
        if (old == GRID - 1) {
            g_bar = 0;               // reset for next replay
            __threadfence();
            atomicAdd(&g_gen, 1u);   // release everyone
        } else {
            while (*(volatile unsigned int*)&g_gen == start) { }
        }
        bar_gen = 1;
    }
    __syncthreads();
    __threadfence();                 // acquire side
    (void)bar_gen;

    // ---------------- Phase 2: pipelined element energy ------------------
    float facc = 0.0f;
    Gath g_cur = load_gather(s_cur.cab);

    #pragma unroll
    for (int i = 0; i < NITER; i++) {
        Gath   g_nxt;
        Stream s_aft;
        if (i + 1 < NITER)
            g_nxt = load_gather(s_nxt.cab);            // cab arrived 1 iter ago
        if (i + 2 < NITER)
            s_aft = load_stream(tid + (i + 2) * NTH,
                                c4, L2p, E2p, A2p, I2p, d2p);

        facc += pair_energy(s_cur, g_cur);             // overlaps in-flight loads

        s_cur = s_nxt;
        if (i + 2 < NITER) s_nxt = s_aft;
        if (i + 1 < NITER) g_cur = g_nxt;
    }

    acc += 0.5 * (double)facc;

    // ---------------- Final reduction ------------------------------------
    double bsum = block_reduce_add(acc);

    __shared__ bool is_last;
    if (threadIdx.x == 0) {
        g_partials[blockIdx.x] = bsum;
        __threadfence();
        unsigned int done = atomicAdd(&g_count, 1u);
        is_last = (done == GRID - 1);
    }
    __syncthreads();

    if (is_last) {
        double v = 0.0;
        for (int b = threadIdx.x; b < GRID; b += TPB)
            v += g_partials[b];
        double total = block_reduce_add(v);
        if (threadIdx.x == 0) {
            double E_c = fmax((double)__ldg(F_c_p) * (double)u_c, 1e-30);
            out[0] = (float)(total / E_c);
            __threadfence();
            g_count = 0;  // replay-safe reset
        }
    }
}

extern "C" void kernel_launch(void* const* d_in, const int* in_sizes, int n_in,
                              void* d_out, int out_size) {
    const float* pred  = (const float*)d_in[0];
    const float* Lv    = (const float*)d_in[1];
    const float* Ev    = (const float*)d_in[2];
    const float* Av    = (const float*)d_in[3];
    const float* Iv    = (const float*)d_in[4];
    const float* dir   = (const float*)d_in[5];
    const float* Fext  = (const float*)d_in[6];
    const float* u_c   = (const float*)d_in[7];
    const float* th_c  = (const float*)d_in[8];
    const float* F_c   = (const float*)d_in[9];
    const int*   conn  = (const int*)d_in[10];
    float* out = (float*)d_out;

    fused_energy_kernel<<<GRID, TPB>>>(
        pred, Lv, Ev, Av, Iv, dir, conn, Fext, u_c, th_c, F_c, out);
}